// round 15
// baseline (speedup 1.0000x reference)
#include <cuda_runtime.h>
#include <cuda_bf16.h>
#include <cstdint>

// ---------------- problem constants ----------------
#define NB 16        // batch
#define NC 80        // classes
#define NP 17064     // total locations across 5 levels
#define NP4 (NP / 4) // 4266
#define PRE_K 1000
#define POST_K 100
#define CAND 2048
#define HBINS 4096
#define IMG_W_F 1024.0f
#define IMG_H_F 800.0f
#define THRESH_F 0.05f
#define IOU_THR_F 0.6f
#define CLS_OFF_F 4096.0f

struct Ptrs {
    const float* cls[5];
    const float* reg[5];
    const float* ctr[5];
};

// ---------------- device scratch (static, no allocs; zero-initialized) ----------------
__device__ float    g_scores[NB * NP];
__device__ int      g_labels[NB * NP];
__device__ float    g_boxes [NB * NP * 4];
__device__ float    g_tscore[NB * PRE_K];
__device__ int      g_tlabel[NB * PRE_K];
__device__ float    g_tbox  [NB * PRE_K * 4];
// row-major mask: g_mask[(n*PRE_K + i)*32 + w] = suppression word (j-chunk w) by box i.
// words with w*32+31 <= i are never written by any run -> stay zero (triangular invariant).
__device__ unsigned g_mask  [NB * PRE_K * 32];
__device__ unsigned g_validw[NB * 32];

__device__ __forceinline__ float sigmoidf_(float x) {
    return 1.0f / (1.0f + expf(-x));
}

// ============ Kernel 1: decode; 4 locations x 20 classes per thread ============
__global__ void __launch_bounds__(256) k_decode(Ptrs p) {
    const unsigned FULL = 0xFFFFFFFFu;
    int t = blockIdx.x * blockDim.x + threadIdx.x;
    int g = t >> 2;                      // location-group id
    int q = t & 3;                       // class-chunk id
    if (g >= NB * NP4) return;
    int n = g / NP4;
    int loc = (g - n * NP4) * 4;

    int l, off, ww, stride, hw;
    if (loc < 12800)      { l = 0; off = 0;     ww = 128; stride = 8;   hw = 12800; }
    else if (loc < 16000) { l = 1; off = 12800; ww = 64;  stride = 16;  hw = 3200;  }
    else if (loc < 16800) { l = 2; off = 16000; ww = 32;  stride = 32;  hw = 800;   }
    else if (loc < 17008) { l = 3; off = 16800; ww = 16;  stride = 64;  hw = 208;   }
    else                  { l = 4; off = 17008; ww = 8;   stride = 128; hw = 56;    }

    int local = loc - off;               // multiple of 4; same row (ww % 4 == 0)
    int y = local / ww;
    int x = local - y * ww;

    // partial argmax over classes [q*20, q*20+20)
    const float4* cls = (const float4*)(p.cls[l] + (size_t)n * NC * hw
                                        + (size_t)(q * 20) * hw + local);
    size_t cstride = (size_t)hw / 4;
    float4 m0 = __ldg(&cls[0]);
    float mv[4] = {m0.x, m0.y, m0.z, m0.w};
    int   mi[4] = {q * 20, q * 20, q * 20, q * 20};
#pragma unroll
    for (int c = 1; c < 20; c++) {
        float4 v = __ldg(&cls[(size_t)c * cstride]);
        if (v.x > mv[0]) { mv[0] = v.x; mi[0] = q * 20 + c; }
        if (v.y > mv[1]) { mv[1] = v.y; mi[1] = q * 20 + c; }
        if (v.z > mv[2]) { mv[2] = v.z; mi[2] = q * 20 + c; }
        if (v.w > mv[3]) { mv[3] = v.w; mi[3] = q * 20 + c; }
    }

    // combine chunks: step 1 (xor 1), step 2 (xor 2)
#pragma unroll
    for (int k = 0; k < 4; k++) {
        float ov = __shfl_xor_sync(FULL, mv[k], 1);
        int   oi = __shfl_xor_sync(FULL, mi[k], 1);
        bool take = (q & 1) ? (ov >= mv[k]) : (ov > mv[k]);
        if (take) { mv[k] = ov; mi[k] = oi; }
    }
#pragma unroll
    for (int k = 0; k < 4; k++) {
        float ov = __shfl_xor_sync(FULL, mv[k], 2);
        int   oi = __shfl_xor_sync(FULL, mi[k], 2);
        bool take = (q & 2) ? (ov >= mv[k]) : (ov > mv[k]);
        if (take) { mv[k] = ov; mi[k] = oi; }
    }

    if (q != 0) return;

    float4 ctr = __ldg((const float4*)(p.ctr[l] + (size_t)n * hw + local));
    const float* reg = p.reg[l] + (size_t)n * 4 * hw + local;
    float4 dl = __ldg((const float4*)(reg));
    float4 dt = __ldg((const float4*)(reg + hw));
    float4 dr = __ldg((const float4*)(reg + 2 * hw));
    float4 db = __ldg((const float4*)(reg + 3 * hw));

    float py = (float)y * (float)stride + 0.5f * (float)stride;
    float ctv[4] = {ctr.x, ctr.y, ctr.z, ctr.w};
    float dlv[4] = {dl.x, dl.y, dl.z, dl.w};
    float dtv[4] = {dt.x, dt.y, dt.z, dt.w};
    float drv[4] = {dr.x, dr.y, dr.z, dr.w};
    float dbv[4] = {db.x, db.y, db.z, db.w};
    float sc[4]; float4 box[4];
#pragma unroll
    for (int k = 0; k < 4; k++) {
        float s = sqrtf(sigmoidf_(mv[k]) * sigmoidf_(ctv[k]));
        if (!(s > THRESH_F)) s = 0.0f;
        float px = (float)(x + k) * (float)stride + 0.5f * (float)stride;
        float x1 = fminf(fmaxf(px - dlv[k], 0.0f), IMG_W_F);
        float y1 = fminf(fmaxf(py - dtv[k], 0.0f), IMG_H_F);
        float x2 = fminf(fmaxf(px + drv[k], 0.0f), IMG_W_F);
        float y2 = fminf(fmaxf(py + dbv[k], 0.0f), IMG_H_F);
        sc[k] = s;
        box[k] = make_float4(x1, y1, x2, y2);
    }

    int base = n * NP + loc;
    *(float4*)&g_scores[base] = make_float4(sc[0], sc[1], sc[2], sc[3]);
    *(int4*)&g_labels[base]   = make_int4(mi[0], mi[1], mi[2], mi[3]);
    float4* bout = (float4*)&g_boxes[(size_t)base * 4];
    bout[0] = box[0]; bout[1] = box[1]; bout[2] = box[2]; bout[3] = box[3];
}

// ============ Kernel 2: fused top-K select + sort (per batch) ============
__global__ void __launch_bounds__(1024) k_topk() {
    __shared__ int hist[HBINS];                 // 16 KB
    __shared__ unsigned long long key[CAND];    // 16 KB
    __shared__ int wt[32];
    __shared__ int wsuf[32];
    __shared__ int sB, sCnt;

    int n = blockIdx.x;
    int tid = threadIdx.x;
    int lane = tid & 31;
    int warp = tid >> 5;
    const unsigned FULL = 0xFFFFFFFFu;

    for (int i = tid; i < HBINS; i += 1024) hist[i] = 0;
    __syncthreads();

    // pass A: linear histogram of scores, float4 (scores in [0,1))
    const float4* sc4 = (const float4*)&g_scores[n * NP];
    for (int p4 = tid; p4 < NP4; p4 += 1024) {
        float4 s4 = sc4[p4];
        atomicAdd(&hist[min((int)(s4.x * (float)HBINS), HBINS - 1)], 1);
        atomicAdd(&hist[min((int)(s4.y * (float)HBINS), HBINS - 1)], 1);
        atomicAdd(&hist[min((int)(s4.z * (float)HBINS), HBINS - 1)], 1);
        atomicAdd(&hist[min((int)(s4.w * (float)HBINS), HBINS - 1)], 1);
    }
    __syncthreads();

    // chunk sums: thread t owns bins [t*4, t*4+4)
    int b0 = tid * 4;
    int c = 0;
#pragma unroll
    for (int k = 0; k < 4; k++) c += hist[b0 + k];
    int x = c;
    for (int d = 1; d < 32; d <<= 1) {
        int y = __shfl_down_sync(FULL, x, d);
        if (lane + d < 32) x += y;
    }
    if (lane == 0) wt[warp] = x;
    __syncthreads();
    if (warp == 0) {
        int t = wt[lane];
        int xx = t;
        for (int d = 1; d < 32; d <<= 1) {
            int y = __shfl_down_sync(FULL, xx, d);
            if (lane + d < 32) xx += y;
        }
        wsuf[lane] = xx - t;
    }
    if (tid == 0) sCnt = 0;
    __syncthreads();

    int S = wsuf[warp] + (x - c);
    if (S < PRE_K && S + c >= PRE_K) {
        int acc = S;
        for (int k = 3; k >= 0; k--) {
            acc += hist[b0 + k];
            if (acc >= PRE_K) { sB = b0 + k; break; }
        }
    }
    __syncthreads();
    int B = sB;

    // pass B: collect candidates with bin >= B into smem keys (float4)
    for (int p4 = tid; p4 < NP4; p4 += 1024) {
        float4 s4 = sc4[p4];
        float sv[4] = {s4.x, s4.y, s4.z, s4.w};
#pragma unroll
        for (int e = 0; e < 4; e++) {
            int b = min((int)(sv[e] * (float)HBINS), HBINS - 1);
            if (b >= B) {
                int pos = atomicAdd(&sCnt, 1);
                if (pos < CAND) {
                    int p = p4 * 4 + e;
                    key[pos] = ((unsigned long long)__float_as_uint(sv[e]) << 32)
                             | (unsigned)(~(unsigned)p);
                }
            }
        }
    }
    __syncthreads();
    int cnt = min(sCnt, CAND);
    for (int i = cnt + tid; i < CAND; i += 1024) key[i] = 0ull;
    __syncthreads();

    // bitonic sort desc; width 1024 when candidates fit (usual case), else 2048
    int sortN = (cnt <= 1024) ? 1024 : CAND;
    int epm = sortN >> 10;                       // elements per thread (1 or 2)
    for (int k = 2; k <= sortN; k <<= 1) {
        for (int j = k >> 1; j > 0; j >>= 1) {
            for (int e = 0; e < epm; e++) {
                int idx = tid + e * 1024;
                int ixj = idx ^ j;
                if (ixj > idx) {
                    unsigned long long a = key[idx], b2 = key[ixj];
                    bool desc = (idx & k) == 0;
                    if ((a < b2) == desc) { key[idx] = b2; key[ixj] = a; }
                }
            }
            __syncthreads();
        }
    }

    // output top-1000 + valid words
    unsigned long long kk = (tid < PRE_K) ? key[tid] : 0ull;
    float s = __uint_as_float((unsigned)(kk >> 32));
    unsigned bal = __ballot_sync(FULL, (tid < PRE_K) && (s > 0.0f));
    if (lane == 0) g_validw[n * 32 + warp] = bal;
    if (tid < PRE_K) {
        int src_idx = (int)(~(unsigned)(kk & 0xFFFFFFFFull));
        int d = n * PRE_K + tid;
        g_tscore[d] = s;
        g_tlabel[d] = g_labels[n * NP + src_idx];
        *(float4*)&g_tbox[(size_t)d * 4] =
            *(const float4*)&g_boxes[((size_t)n * NP + src_idx) * 4];
    }
}

// ============ Kernel 3: suppression mask (row-major layout, striped rows) ============
__global__ void k_mask() {
    __shared__ float4 sbox[1024];
    int n = blockIdx.x;
    int iblk = blockIdx.y;
    int tid = threadIdx.x;
    const unsigned FULL = 0xFFFFFFFFu;

    for (int i = tid; i < 1024; i += blockDim.x) {
        float4 b;
        if (i < PRE_K) {
            b = *(const float4*)&g_tbox[((size_t)n * PRE_K + i) * 4];
            float o = (float)g_tlabel[n * PRE_K + i] * CLS_OFF_F;
            b.x += o; b.y += o; b.z += o; b.w += o;
        } else {
            b = make_float4(0.f, 0.f, 0.f, 0.f);   // zero box -> iou = 0
        }
        sbox[i] = b;
    }
    __syncthreads();

    int w = tid >> 5;
    int lane = tid & 31;
    int j = w * 32 + lane;
    float4 jb = sbox[j];
    float ja = (jb.z - jb.x) * (jb.w - jb.y);

    int imax = w * 32 + 31;                  // rows i >= imax have no j>i in chunk
    int ilim = min(PRE_K, imax);
    int tmax = (ilim - iblk + 7) >> 3;       // i = iblk + 8t < ilim
    if (tmax < 0) tmax = 0;
    unsigned* mrow = &g_mask[((size_t)n * PRE_K) * 32 + w];

#pragma unroll 2
    for (int t = 0; t < tmax; t++) {
        int i = iblk + t * 8;
        float4 ib = sbox[i];                 // broadcast, conflict-free
        float ia = (ib.z - ib.x) * (ib.w - ib.y);
        float xx1 = fmaxf(ib.x, jb.x);
        float yy1 = fmaxf(ib.y, jb.y);
        float xx2 = fminf(ib.z, jb.z);
        float yy2 = fminf(ib.w, jb.w);
        float iw = fmaxf(xx2 - xx1, 0.0f);
        float ih = fmaxf(yy2 - yy1, 0.0f);
        float inter = iw * ih;
        float iou = inter / (ia + ja - inter + 1e-9f);
        unsigned bal = __ballot_sync(FULL, iou > IOU_THR_F);
        if (lane == 0) {
            if ((i >> 5) == w) bal &= ~((2u << (i & 31)) - 1u);   // clear j <= i
            mrow[(size_t)i * 32] = bal;
        }
    }
}

// ============ Kernel 4: warp-ring greedy sweep (registers + named barriers) ============
// 16 warps; warp k owns tiles W=2k, 2k+1 with columns preloaded via COALESCED
// row loads: colX[b] = g_mask[(W*32+b)][lane]. Serial chain through named
// barriers; valid vector handed off via smem sv[32].
__global__ void __launch_bounds__(512, 1) k_sweep(float* out) {
    __shared__ unsigned sv[32];
    __shared__ int s_sel [POST_K];
    __shared__ int s_kept[POST_K];

    int n = blockIdx.x;
    int tid = threadIdx.x;
    int lane = tid & 31;
    int warp = tid >> 5;
    const unsigned FULL = 0xFFFFFFFFu;

    const unsigned* mb = &g_mask[(size_t)n * PRE_K * 32];
    int WA = warp * 2;
    int WB = warp * 2 + 1;

    // preload both tiles' columns (coalesced 128B row loads -> registers)
    unsigned colA[32], colB[32];
#pragma unroll
    for (int b = 0; b < 32; b++)
        colA[b] = __ldg(&mb[(size_t)(WA * 32 + b) * 32 + lane]);   // i <= 991 < PRE_K
#pragma unroll
    for (int b = 0; b < 32; b++) {
        int i = WB * 32 + b;
        colB[b] = (i < PRE_K) ? __ldg(&mb[(size_t)i * 32 + lane]) : 0u;
    }

    unsigned v;
    if (warp == 0) {
        v = g_validw[n * 32 + lane];
    } else {
        asm volatile("bar.sync %0, 64;" :: "r"(warp) : "memory");
        v = sv[lane];
    }

    // tile WA
    {
        unsigned vw = __shfl_sync(FULL, v, WA);
        if (vw != 0) {
            unsigned alive = vw;
#pragma unroll
            for (int b = 0; b < 32; b++)
                if ((alive >> b) & 1u) alive &= ~colA[b];
            alive = __shfl_sync(FULL, alive, WA);   // lane WA's column is the diagonal
            if (lane == WA) v = alive;
#pragma unroll
            for (int b = 0; b < 32; b++)
                if ((alive >> b) & 1u) v &= ~colA[b];
        }
    }
    // tile WB
    {
        unsigned vw = __shfl_sync(FULL, v, WB);
        if (vw != 0) {
            unsigned alive = vw;
#pragma unroll
            for (int b = 0; b < 32; b++)
                if ((alive >> b) & 1u) alive &= ~colB[b];
            alive = __shfl_sync(FULL, alive, WB);
            if (lane == WB) v = alive;
#pragma unroll
            for (int b = 0; b < 32; b++)
                if ((alive >> b) & 1u) v &= ~colB[b];
        }
    }

    if (warp < 15) {
        sv[lane] = v;
        asm volatile("bar.sync %0, 64;" :: "r"(warp + 1) : "memory");
    } else {
        // final partition (kept in index order, then dropped in index order)
        int c = __popc(v);
        int incl = c;
        for (int d = 1; d < 32; d <<= 1) {
            int t = __shfl_up_sync(FULL, incl, d);
            if (lane >= d) incl += t;
        }
        int pre = incl - c;
        int totK = __shfl_sync(FULL, incl, 31);
        for (int b = 0; b < 32; b++) {
            int i = lane * 32 + b;
            if (i >= PRE_K) break;
            bool kept = (v >> b) & 1u;
            int kb = pre + __popc(v & ((1u << b) - 1u));
            int pos = kept ? kb : (totK + (i - kb));
            if (pos < POST_K) { s_sel[pos] = i; s_kept[pos] = kept ? 1 : 0; }
        }
    }
    __syncthreads();

    if (tid < POST_K) {
        int i = s_sel[tid];
        int kept = s_kept[tid];
        int src = n * PRE_K + i;
        int dst = n * POST_K + tid;
        float4 b = *(const float4*)&g_tbox[(size_t)src * 4];
        ((float4*)out)[dst] = b;
        out[NB * POST_K * 4 + dst] = kept ? g_tscore[src] : 0.0f;          // scores
        out[NB * POST_K * 4 + NB * POST_K + dst] = (float)g_tlabel[src];   // labels
    }
}

// ---------------- host launch ----------------
extern "C" void kernel_launch(void* const* d_in, const int* in_sizes, int n_in,
                              void* d_out, int out_size) {
    (void)in_sizes; (void)n_in; (void)out_size;

    Ptrs p;
    for (int l = 0; l < 5; l++) {
        p.cls[l] = (const float*)d_in[3 * l + 0];
        p.reg[l] = (const float*)d_in[3 * l + 1];
        p.ctr[l] = (const float*)d_in[3 * l + 2];
    }
    float* out = (float*)d_out;

    int total = NB * NP4 * 4;
    k_decode<<<(total + 255) / 256, 256>>>(p);
    k_topk<<<NB, 1024>>>();
    k_mask<<<dim3(NB, 8), 1024>>>();
    k_sweep<<<NB, 512>>>(out);
}

// round 16
// speedup vs baseline: 1.1258x; 1.1258x over previous
#include <cuda_runtime.h>
#include <cuda_bf16.h>
#include <cstdint>

// ---------------- problem constants ----------------
#define NB 16        // batch
#define NC 80        // classes
#define NP 17064     // total locations across 5 levels
#define NP4 (NP / 4) // 4266
#define PRE_K 1000
#define POST_K 100
#define CAND 2048
#define HBINS 4096
#define IMG_W_F 1024.0f
#define IMG_H_F 800.0f
#define THRESH_F 0.05f
#define IOU_THR_F 0.6f
#define CLS_OFF_F 4096.0f

struct Ptrs {
    const float* cls[5];
    const float* reg[5];
    const float* ctr[5];
};

// ---------------- device scratch (static, no allocs; zero-initialized) ----------------
__device__ float    g_scores[NB * NP];
__device__ int      g_labels[NB * NP];
__device__ float    g_boxes [NB * NP * 4];
__device__ float    g_tscore[NB * PRE_K];
__device__ int      g_tlabel[NB * PRE_K];
__device__ float    g_tbox  [NB * PRE_K * 4];
// transposed mask: g_maskT[(n*32 + w) * 1024 + i]; rows never written stay zero.
__device__ unsigned g_maskT [NB * 32 * 1024];
__device__ unsigned g_validw[NB * 32];
// per-batch score histogram; zeroed at start of k_sweep for the next launch
// (zero-initialized statically for the very first launch).
__device__ int      g_hist  [NB * HBINS];

__device__ __forceinline__ float sigmoidf_(float x) {
    return 1.0f / (1.0f + expf(-x));
}

// ============ Kernel 1: decode; 4 locations x 20 classes per thread + hist ============
__global__ void __launch_bounds__(256) k_decode(Ptrs p) {
    const unsigned FULL = 0xFFFFFFFFu;
    int t = blockIdx.x * blockDim.x + threadIdx.x;
    int g = t >> 2;                      // location-group id
    int q = t & 3;                       // class-chunk id
    if (g >= NB * NP4) return;
    int n = g / NP4;
    int loc = (g - n * NP4) * 4;

    int l, off, ww, stride, hw;
    if (loc < 12800)      { l = 0; off = 0;     ww = 128; stride = 8;   hw = 12800; }
    else if (loc < 16000) { l = 1; off = 12800; ww = 64;  stride = 16;  hw = 3200;  }
    else if (loc < 16800) { l = 2; off = 16000; ww = 32;  stride = 32;  hw = 800;   }
    else if (loc < 17008) { l = 3; off = 16800; ww = 16;  stride = 64;  hw = 208;   }
    else                  { l = 4; off = 17008; ww = 8;   stride = 128; hw = 56;    }

    int local = loc - off;               // multiple of 4; same row (ww % 4 == 0)
    int y = local / ww;
    int x = local - y * ww;

    // partial argmax over classes [q*20, q*20+20)
    const float4* cls = (const float4*)(p.cls[l] + (size_t)n * NC * hw
                                        + (size_t)(q * 20) * hw + local);
    size_t cstride = (size_t)hw / 4;
    float4 m0 = __ldg(&cls[0]);
    float mv[4] = {m0.x, m0.y, m0.z, m0.w};
    int   mi[4] = {q * 20, q * 20, q * 20, q * 20};
#pragma unroll
    for (int c = 1; c < 20; c++) {
        float4 v = __ldg(&cls[(size_t)c * cstride]);
        if (v.x > mv[0]) { mv[0] = v.x; mi[0] = q * 20 + c; }
        if (v.y > mv[1]) { mv[1] = v.y; mi[1] = q * 20 + c; }
        if (v.z > mv[2]) { mv[2] = v.z; mi[2] = q * 20 + c; }
        if (v.w > mv[3]) { mv[3] = v.w; mi[3] = q * 20 + c; }
    }

    // combine chunks: step 1 (xor 1), step 2 (xor 2)
#pragma unroll
    for (int k = 0; k < 4; k++) {
        float ov = __shfl_xor_sync(FULL, mv[k], 1);
        int   oi = __shfl_xor_sync(FULL, mi[k], 1);
        bool take = (q & 1) ? (ov >= mv[k]) : (ov > mv[k]);
        if (take) { mv[k] = ov; mi[k] = oi; }
    }
#pragma unroll
    for (int k = 0; k < 4; k++) {
        float ov = __shfl_xor_sync(FULL, mv[k], 2);
        int   oi = __shfl_xor_sync(FULL, mi[k], 2);
        bool take = (q & 2) ? (ov >= mv[k]) : (ov > mv[k]);
        if (take) { mv[k] = ov; mi[k] = oi; }
    }

    if (q != 0) return;

    float4 ctr = __ldg((const float4*)(p.ctr[l] + (size_t)n * hw + local));
    const float* reg = p.reg[l] + (size_t)n * 4 * hw + local;
    float4 dl = __ldg((const float4*)(reg));
    float4 dt = __ldg((const float4*)(reg + hw));
    float4 dr = __ldg((const float4*)(reg + 2 * hw));
    float4 db = __ldg((const float4*)(reg + 3 * hw));

    float py = (float)y * (float)stride + 0.5f * (float)stride;
    float ctv[4] = {ctr.x, ctr.y, ctr.z, ctr.w};
    float dlv[4] = {dl.x, dl.y, dl.z, dl.w};
    float dtv[4] = {dt.x, dt.y, dt.z, dt.w};
    float drv[4] = {dr.x, dr.y, dr.z, dr.w};
    float dbv[4] = {db.x, db.y, db.z, db.w};
    float sc[4]; float4 box[4];
#pragma unroll
    for (int k = 0; k < 4; k++) {
        float s = sqrtf(sigmoidf_(mv[k]) * sigmoidf_(ctv[k]));
        if (!(s > THRESH_F)) s = 0.0f;
        float px = (float)(x + k) * (float)stride + 0.5f * (float)stride;
        float x1 = fminf(fmaxf(px - dlv[k], 0.0f), IMG_W_F);
        float y1 = fminf(fmaxf(py - dtv[k], 0.0f), IMG_H_F);
        float x2 = fminf(fmaxf(px + drv[k], 0.0f), IMG_W_F);
        float y2 = fminf(fmaxf(py + dbv[k], 0.0f), IMG_H_F);
        sc[k] = s;
        box[k] = make_float4(x1, y1, x2, y2);
    }

    // fused histogram pass (per-batch, global atomics; ~4-way bin contention)
    int hb = n * HBINS;
#pragma unroll
    for (int k = 0; k < 4; k++) {
        int b = min((int)(sc[k] * (float)HBINS), HBINS - 1);
        atomicAdd(&g_hist[hb + b], 1);
    }

    int base = n * NP + loc;
    *(float4*)&g_scores[base] = make_float4(sc[0], sc[1], sc[2], sc[3]);
    *(int4*)&g_labels[base]   = make_int4(mi[0], mi[1], mi[2], mi[3]);
    float4* bout = (float4*)&g_boxes[(size_t)base * 4];
    bout[0] = box[0]; bout[1] = box[1]; bout[2] = box[2]; bout[3] = box[3];
}

// ============ Kernel 2: top-K select + hybrid bitonic sort (per batch) ============
__device__ __forceinline__ unsigned long long shflx64(unsigned long long v, int m) {
    return __shfl_xor_sync(0xFFFFFFFFu, v, m);
}

__global__ void __launch_bounds__(1024) k_topk() {
    __shared__ unsigned long long key[CAND];    // 16 KB
    __shared__ int wt[32];
    __shared__ int wsuf[32];
    __shared__ int sB, sCnt;

    int n = blockIdx.x;
    int tid = threadIdx.x;
    int lane = tid & 31;
    int warp = tid >> 5;
    const unsigned FULL = 0xFFFFFFFFu;

    // chunk sums from the decode-built global histogram (thread t owns bins [4t,4t+4))
    const int* hist = &g_hist[n * HBINS];
    int4 h4 = __ldg((const int4*)hist + tid);
    int hv[4] = {h4.x, h4.y, h4.z, h4.w};
    int c = hv[0] + hv[1] + hv[2] + hv[3];
    int x = c;
    for (int d = 1; d < 32; d <<= 1) {
        int y = __shfl_down_sync(FULL, x, d);
        if (lane + d < 32) x += y;
    }
    if (lane == 0) wt[warp] = x;
    __syncthreads();
    if (warp == 0) {
        int t = wt[lane];
        int xx = t;
        for (int d = 1; d < 32; d <<= 1) {
            int y = __shfl_down_sync(FULL, xx, d);
            if (lane + d < 32) xx += y;
        }
        wsuf[lane] = xx - t;
    }
    if (tid == 0) sCnt = 0;
    __syncthreads();

    int S = wsuf[warp] + (x - c);    // elements in bins above this chunk
    if (S < PRE_K && S + c >= PRE_K) {
        int acc = S;
        for (int k = 3; k >= 0; k--) {
            acc += hv[k];
            if (acc >= PRE_K) { sB = tid * 4 + k; break; }
        }
    }
    __syncthreads();
    int B = sB;

    // collect candidates with bin >= B into smem keys (float4)
    const float4* sc4 = (const float4*)&g_scores[n * NP];
    for (int p4 = tid; p4 < NP4; p4 += 1024) {
        float4 s4 = sc4[p4];
        float sv[4] = {s4.x, s4.y, s4.z, s4.w};
#pragma unroll
        for (int e = 0; e < 4; e++) {
            int b = min((int)(sv[e] * (float)HBINS), HBINS - 1);
            if (b >= B) {
                int pos = atomicAdd(&sCnt, 1);
                if (pos < CAND) {
                    int p = p4 * 4 + e;
                    key[pos] = ((unsigned long long)__float_as_uint(sv[e]) << 32)
                             | (unsigned)(~(unsigned)p);
                }
            }
        }
    }
    __syncthreads();
    int cnt = min(sCnt, CAND);
    for (int i = cnt + tid; i < CAND; i += 1024) key[i] = 0ull;
    __syncthreads();

    if (cnt <= 1024) {
        // hybrid bitonic desc over 1024 keys: intra-warp stages (j<=16) via shfl
        unsigned long long kk = key[tid];
        // k = 2..16 entirely in registers
#pragma unroll
        for (int k = 2; k <= 16; k <<= 1) {
#pragma unroll 4
            for (int j = k >> 1; j > 0; j >>= 1) {
                unsigned long long pk = shflx64(kk, j);
                bool desc = (tid & k) == 0;
                bool lower = (tid & j) == 0;
                bool takeMax = (lower == desc);
                kk = takeMax ? (kk > pk ? kk : pk) : (kk < pk ? kk : pk);
            }
        }
        key[tid] = kk;
        __syncthreads();
        for (int k = 32; k <= 1024; k <<= 1) {
            for (int j = k >> 1; j >= 32; j >>= 1) {
                int ixj = tid ^ j;
                if (ixj > tid) {
                    unsigned long long a = key[tid], b2 = key[ixj];
                    bool desc = (tid & k) == 0;
                    if ((a < b2) == desc) { key[tid] = b2; key[ixj] = a; }
                }
                __syncthreads();
            }
            kk = key[tid];
            bool desc = (tid & k) == 0;
#pragma unroll
            for (int j = 16; j > 0; j >>= 1) {
                unsigned long long pk = shflx64(kk, j);
                bool lower = (tid & j) == 0;
                bool takeMax = (lower == desc);
                kk = takeMax ? (kk > pk ? kk : pk) : (kk < pk ? kk : pk);
            }
            key[tid] = kk;
            __syncthreads();
        }
    } else {
        // fallback: classic 2048-wide bitonic, 2 elements per thread
        for (int k = 2; k <= CAND; k <<= 1) {
            for (int j = k >> 1; j > 0; j >>= 1) {
#pragma unroll
                for (int e = 0; e < 2; e++) {
                    int idx = tid + e * 1024;
                    int ixj = idx ^ j;
                    if (ixj > idx) {
                        unsigned long long a = key[idx], b2 = key[ixj];
                        bool desc = (idx & k) == 0;
                        if ((a < b2) == desc) { key[idx] = b2; key[ixj] = a; }
                    }
                }
                __syncthreads();
            }
        }
    }

    // output top-1000 + valid words
    unsigned long long kk = (tid < PRE_K) ? key[tid] : 0ull;
    float s = __uint_as_float((unsigned)(kk >> 32));
    unsigned bal = __ballot_sync(FULL, (tid < PRE_K) && (s > 0.0f));
    if (lane == 0) g_validw[n * 32 + warp] = bal;
    if (tid < PRE_K) {
        int src_idx = (int)(~(unsigned)(kk & 0xFFFFFFFFull));
        int d = n * PRE_K + tid;
        g_tscore[d] = s;
        g_tlabel[d] = g_labels[n * NP + src_idx];
        *(float4*)&g_tbox[(size_t)d * 4] =
            *(const float4*)&g_boxes[((size_t)n * NP + src_idx) * 4];
    }
}

// ============ Kernel 3: suppression mask (transposed layout, striped rows) ============
__global__ void k_mask() {
    __shared__ float4 sbox[1024];
    int n = blockIdx.x;
    int iblk = blockIdx.y;
    int tid = threadIdx.x;
    const unsigned FULL = 0xFFFFFFFFu;

    for (int i = tid; i < 1024; i += blockDim.x) {
        float4 b;
        if (i < PRE_K) {
            b = *(const float4*)&g_tbox[((size_t)n * PRE_K + i) * 4];
            float o = (float)g_tlabel[n * PRE_K + i] * CLS_OFF_F;
            b.x += o; b.y += o; b.z += o; b.w += o;
        } else {
            b = make_float4(0.f, 0.f, 0.f, 0.f);   // zero box -> iou = 0
        }
        sbox[i] = b;
    }
    __syncthreads();

    int w = tid >> 5;
    int lane = tid & 31;
    int j = w * 32 + lane;
    float4 jb = sbox[j];
    float ja = (jb.z - jb.x) * (jb.w - jb.y);

    int imax = w * 32 + 31;
    int ilim = min(PRE_K, imax);
    int tmax = (ilim - iblk + 7) >> 3;
    if (tmax < 0) tmax = 0;
    unsigned* mrow = &g_maskT[((size_t)n * 32 + w) * 1024];

#pragma unroll 2
    for (int t = 0; t < tmax; t++) {
        int i = iblk + t * 8;
        float4 ib = sbox[i];
        float ia = (ib.z - ib.x) * (ib.w - ib.y);
        float xx1 = fmaxf(ib.x, jb.x);
        float yy1 = fmaxf(ib.y, jb.y);
        float xx2 = fminf(ib.z, jb.z);
        float yy2 = fminf(ib.w, jb.w);
        float iw = fmaxf(xx2 - xx1, 0.0f);
        float ih = fmaxf(yy2 - yy1, 0.0f);
        float inter = iw * ih;
        float iou = inter / (ia + ja - inter + 1e-9f);
        unsigned bal = __ballot_sync(FULL, iou > IOU_THR_F);
        if (lane == 0) {
            if ((i >> 5) == w) bal &= ~((2u << (i & 31)) - 1u);   // clear j <= i
            mrow[i] = bal;
        }
    }
}

// ============ Kernel 4: greedy sweep (smem-staged, register-hoisted columns) ============
__global__ void __launch_bounds__(1024) k_sweep(float* out) {
    __shared__ unsigned buf[2][32][129];    // 33 KB
    __shared__ int s_sel [POST_K];
    __shared__ int s_kept[POST_K];

    int n = blockIdx.x;
    int tid = threadIdx.x;
    int lane = tid & 31;
    int warp = tid >> 5;
    const unsigned FULL = 0xFFFFFFFFu;

    // zero this batch's histogram for the next launch (consumed earlier this launch)
#pragma unroll
    for (int i = tid; i < HBINS; i += 1024) g_hist[n * HBINS + i] = 0;

    const uint4* gp = (const uint4*)&g_maskT[((size_t)n * 32 + lane) * 1024];
    uint4 mine = gp[warp];                  // ph=0 stage
    {
        unsigned* d = &buf[0][lane][warp * 4];
        d[0] = mine.x; d[1] = mine.y; d[2] = mine.z; d[3] = mine.w;
    }
    __syncthreads();

    unsigned v = (tid < 32) ? g_validw[n * 32 + lane] : 0u;

#pragma unroll 1
    for (int ph = 0; ph < 8; ph++) {
        if (ph < 7) mine = gp[(ph + 1) * 32 + warp];

        if (tid < 32) {
            const unsigned (&tile)[32][129] = *(const unsigned (*)[32][129])&buf[ph & 1];
#pragma unroll
            for (int t = 0; t < 4; t++) {
                int W = ph * 4 + t;
                unsigned vw = __shfl_sync(FULL, v, W);
                if (vw == 0) continue;
                int cbase = t * 32;
                unsigned col[32];
#pragma unroll
                for (int b = 0; b < 32; b++) col[b] = tile[lane][cbase + b];
                unsigned alive = vw;
#pragma unroll
                for (int b = 0; b < 32; b++)
                    if ((alive >> b) & 1u) alive &= ~col[b];
                alive = __shfl_sync(FULL, alive, W);
                if (lane == W) v = alive;
#pragma unroll
                for (int b = 0; b < 32; b++)
                    if ((alive >> b) & 1u) v &= ~col[b];
            }
        }
        __syncthreads();
        if (ph < 7) {
            unsigned* d = &buf[(ph + 1) & 1][lane][warp * 4];
            d[0] = mine.x; d[1] = mine.y; d[2] = mine.z; d[3] = mine.w;
        }
        __syncthreads();
    }

    if (tid < 32) {
        int c = __popc(v);
        int incl = c;
        for (int d = 1; d < 32; d <<= 1) {
            int t = __shfl_up_sync(FULL, incl, d);
            if (lane >= d) incl += t;
        }
        int pre = incl - c;
        int totK = __shfl_sync(FULL, incl, 31);
        for (int b = 0; b < 32; b++) {
            int i = lane * 32 + b;
            if (i >= PRE_K) break;
            bool kept = (v >> b) & 1u;
            int kb = pre + __popc(v & ((1u << b) - 1u));
            int pos = kept ? kb : (totK + (i - kb));
            if (pos < POST_K) { s_sel[pos] = i; s_kept[pos] = kept ? 1 : 0; }
        }
    }
    __syncthreads();

    if (tid < POST_K) {
        int i = s_sel[tid];
        int kept = s_kept[tid];
        int src = n * PRE_K + i;
        int dst = n * POST_K + tid;
        float4 b = *(const float4*)&g_tbox[(size_t)src * 4];
        ((float4*)out)[dst] = b;
        out[NB * POST_K * 4 + dst] = kept ? g_tscore[src] : 0.0f;          // scores
        out[NB * POST_K * 4 + NB * POST_K + dst] = (float)g_tlabel[src];   // labels
    }
}

// ---------------- host launch ----------------
extern "C" void kernel_launch(void* const* d_in, const int* in_sizes, int n_in,
                              void* d_out, int out_size) {
    (void)in_sizes; (void)n_in; (void)out_size;

    Ptrs p;
    for (int l = 0; l < 5; l++) {
        p.cls[l] = (const float*)d_in[3 * l + 0];
        p.reg[l] = (const float*)d_in[3 * l + 1];
        p.ctr[l] = (const float*)d_in[3 * l + 2];
    }
    float* out = (float*)d_out;

    int total = NB * NP4 * 4;
    k_decode<<<(total + 255) / 256, 256>>>(p);
    k_topk<<<NB, 1024>>>();
    k_mask<<<dim3(NB, 8), 1024>>>();
    k_sweep<<<NB, 1024>>>(out);
}